// round 7
// baseline (speedup 1.0000x reference)
#include <cuda_runtime.h>
#include <cstdint>
#include <math_constants.h>

#define NI    1024
#define NC    201
#define TT    100
#define ROW   (NC * TT)           // 20100
#define NTHR  512                 // warps 0-7: labels, warps 8-15: cls/softplus

// -------- scratch (no allocations; zero at module load) --------
__device__ double         g_acc;          // running total (reset in tail)
__device__ float          g_bg3[NI * 3];  // per-bg-row range sums of v
__device__ unsigned char  g_isbg[NI];
__device__ int            g_done;         // completion counter (reset in tail)

// ======================= threefry2x32 (JAX-exact) =======================
__host__ __device__ constexpr uint32_t rotl32(uint32_t x, int r) {
    return (x << r) | (x >> (32 - r));
}
struct TF2 { uint32_t a, b; };

__host__ __device__ constexpr TF2 tf2x32(uint32_t k0, uint32_t k1,
                                         uint32_t x0, uint32_t x1) {
    uint32_t ks2 = k0 ^ k1 ^ 0x1BD11BDAu;
    uint32_t kk[3] = {k0, k1, ks2};
    const int R0[4] = {13, 15, 26, 6};
    const int R1[4] = {17, 29, 16, 24};
    uint32_t v0 = x0 + k0, v1 = x1 + k1;
    for (int i = 0; i < 5; i++) {
        for (int j = 0; j < 4; j++) {
            int r = (i % 2 == 0) ? R0[j] : R1[j];
            v0 += v1; v1 = rotl32(v1, r); v1 ^= v0;
        }
        v0 += kk[(i + 1) % 3];
        v1 += kk[(i + 2) % 3] + (uint32_t)(i + 1);
    }
    return TF2{v0, v1};
}

constexpr TF2      S98 = tf2x32(0u, 42u, 98u, 198u);
constexpr TF2      S99 = tf2x32(0u, 42u, 99u, 199u);
constexpr uint32_t KLA = S98.b, KLB = S99.b;
constexpr TF2      SP0 = tf2x32(KLA, KLB, 0u, 2u);
constexpr TF2      SP1 = tf2x32(KLA, KLB, 1u, 3u);
constexpr uint32_t K1A = SP0.a, K1B = SP1.a;
constexpr uint32_t K2A = SP0.b, K2B = SP1.b;

__device__ __forceinline__ float tf_uniform(uint32_t ka, uint32_t kb, int n) {
    TF2 r = (n < 512) ? tf2x32(ka, kb, (uint32_t)n,         (uint32_t)(n + 512))
                      : tf2x32(ka, kb, (uint32_t)(n - 512), (uint32_t)n);
    uint32_t bits = (n < 512) ? r.a : r.b;
    return __uint_as_float((bits >> 9) | 0x3f800000u) - 1.0f;
}

// ======================= single fused kernel ==============================
__global__ __launch_bounds__(NTHR) void k_all(const float* __restrict__ cls,
                                              const float* __restrict__ labels,
                                              float* __restrict__ out) {
    __shared__ union {
        struct {
            float best[8][100]; int bi[8][100];   // label warps   (6.4 KB)
            float part[NC * 25];                  // softplus warps (20.1 KB)
        } wk;
        struct { int idx[NI]; float u1[NI]; float u2[NI];
                 unsigned char sel[NI]; } tl;     // tail (13.3 KB)
    } u;
    __shared__ int    sLab[TT];
    __shared__ float  sX99[NC];
    __shared__ double sGat[NC];
    __shared__ double sB3[3];
    __shared__ double sRed[16];
    __shared__ int    sLast, sCnt;

    int n    = blockIdx.x;
    int tid  = threadIdx.x;
    int w    = tid >> 5;
    int lane = tid & 31;

    const float* crow = cls + (size_t)n * ROW;

    if (tid < NC) sGat[tid] = 0.0;
    if (tid >= NC && tid < NC + 3) sB3[tid - NC] = 0.0;

    if (w < 8) {
        // ---- label warps: per-warp partial argmax over strided classes ----
        const float* lrow = labels + (size_t)n * ROW;
        if (lane < 25) {
            float b0 = -CUDART_INF_F, b1 = -CUDART_INF_F,
                  b2 = -CUDART_INF_F, b3 = -CUDART_INF_F;
            int i0 = 0, i1 = 0, i2 = 0, i3 = 0;
            #pragma unroll 4
            for (int c = w; c < NC; c += 8) {
                float4 v = __ldg((const float4*)(lrow + c * TT) + lane);
                if (v.x > b0) { b0 = v.x; i0 = c; }
                if (v.y > b1) { b1 = v.y; i1 = c; }
                if (v.z > b2) { b2 = v.z; i2 = c; }
                if (v.w > b3) { b3 = v.w; i3 = c; }
            }
            int t = lane * 4;
            u.wk.best[w][t + 0] = b0; u.wk.bi[w][t + 0] = i0;
            u.wk.best[w][t + 1] = b1; u.wk.bi[w][t + 1] = i1;
            u.wk.best[w][t + 2] = b2; u.wk.bi[w][t + 2] = i2;
            u.wk.best[w][t + 3] = b3; u.wk.bi[w][t + 3] = i3;
        }
    } else {
        // ---- softplus warps: per-(n,c) partial sums ----
        int w8 = w - 8;
        if (lane < 25) {
            #pragma unroll 4
            for (int c = w8; c < NC; c += 8) {
                float4 x = __ldg((const float4*)(crow + c * TT) + lane);
                float m = fmaxf(x.x, 0.f) + fmaxf(x.y, 0.f)
                        + fmaxf(x.z, 0.f) + fmaxf(x.w, 0.f);
                float l = __log2f(1.f + __expf(-fabsf(x.x)))
                        + __log2f(1.f + __expf(-fabsf(x.y)))
                        + __log2f(1.f + __expf(-fabsf(x.z)))
                        + __log2f(1.f + __expf(-fabsf(x.w)));
                u.wk.part[c * 25 + lane] = m + 0.69314718056f * l;
                if (lane == 24) sX99[c] = x.w;     // t = 99
            }
        }
    }
    __syncthreads();

    // ---- combine argmax partials; first-max tie-break (lower c wins) ----
    if (tid < TT) {
        float b = u.wk.best[0][tid]; int bi = u.wk.bi[0][tid];
        #pragma unroll
        for (int ww = 1; ww < 8; ww++) {
            float v = u.wk.best[ww][tid]; int c = u.wk.bi[ww][tid];
            if (v > b || (v == b && c < bi)) { b = v; bi = c; }
        }
        sLab[tid] = bi;
    }
    __syncthreads();

    int  lab99 = sLab[TT - 1];
    bool isbg  = (lab99 == NC - 1);
    if (tid == 0) g_isbg[n] = (unsigned char)isbg;

    // ---- gather: sum_t x[n, lab[t], t] binned per class ----
    if (tid < TT) {
        int lb = sLab[tid];
        atomicAdd(&sGat[lb], (double)__ldg(crow + (size_t)lb * TT + tid));
    }
    __syncthreads();

    // ---- per-class v; in-block wm dot (non-bg) or 3-range sums (bg) ----
    double wv = 0.0;
    if (tid < NC) {
        float s = 0.f;
        #pragma unroll
        for (int i = 0; i < 25; i++) s += u.wk.part[tid * 25 + i];
        float v = s - (float)sGat[tid];
        if (!isbg) {
            float sg = 1.f / (1.f + __expf(-sX99[tid]));
            if (tid == lab99 || sg >= 0.3f) wv = (double)v;
        } else {
            int r = (tid >= 150) ? 2 : (tid >= 50 ? 1 : 0);
            atomicAdd(&sB3[r], (double)v);
        }
    }
    #pragma unroll
    for (int o = 16; o; o >>= 1) wv += __shfl_xor_sync(0xffffffffu, wv, o);
    if (lane == 0) sRed[w] = wv;
    __syncthreads();
    if (tid == 0 && !isbg) {
        double s = 0.0;
        #pragma unroll
        for (int i = 0; i < 16; i++) s += sRed[i];
        atomicAdd(&g_acc, s);
    }
    if (isbg && tid < 3) g_bg3[n * 3 + tid] = (float)sB3[tid];

    // ---------------- completion; last block runs bg tail ----------------
    if (tid == 0) {
        __threadfence();
        int old = atomicAdd(&g_done, 1);
        sLast = (old == NI - 1);
    }
    __syncthreads();
    if (!sLast) return;
    __threadfence();

    if (tid == 0) sCnt = 0;
    __syncthreads();

    // compact bg rows + uniforms (union reuse is safe: past the barrier)
    for (int i = tid; i < NI; i += NTHR) {
        if (__ldcg(&g_isbg[i])) {
            int p = atomicAdd(&sCnt, 1);
            u.tl.idx[p] = i;
            u.tl.u1[p]  = tf_uniform(K1A, K1B, i);
            u.tl.u2[p]  = tf_uniform(K2A, K2B, i);
        }
    }
    __syncthreads();

    int nbg = sCnt;
    int kr  = nbg / 100;            // int(n_bg * 0.01)
    int kc  = nbg / 10;             // int(n_bg * 0.10)

    // stable-argsort ranks among bg rows
    for (int i = tid; i < nbg; i += NTHR) {
        float u1 = u.tl.u1[i], u2 = u.tl.u2[i];
        int   m  = u.tl.idx[i];
        int r1 = 0, r2 = 0;
        for (int j = 0; j < nbg; j++) {
            float a = u.tl.u1[j], b = u.tl.u2[j];
            int  mj = u.tl.idx[j];
            r1 += (a < u1) || (a == u1 && mj < m);
            r2 += (b < u2) || (b == u2 && mj < m);
        }
        u.tl.sel[i] = (unsigned char)((r1 < kr ? 2u : 0u) | (r2 < kc ? 4u : 0u));
    }
    __syncthreads();

    // bg contributions from 3-range sums
    double acc = 0.0;
    for (int i = tid; i < nbg; i += NTHR) {
        const float* G = &g_bg3[u.tl.idx[i] * 3];
        unsigned f = u.tl.sel[i];
        acc += (double)__ldcg(&G[2]);                       // freq+bg: always
        if (f & 2u) acc += (double)__ldcg(&G[0]);           // rare
        if (f & 4u) acc += (double)__ldcg(&G[1]);           // common
    }
    #pragma unroll
    for (int o = 16; o; o >>= 1) acc += __shfl_xor_sync(0xffffffffu, acc, o);
    if (lane == 0) sRed[w] = acc;
    __syncthreads();
    if (tid == 0) {
        double s = 0.0;
        #pragma unroll
        for (int i = 0; i < 16; i++) s += sRed[i];
        double tot = atomicAdd(&g_acc, 0.0) + s;
        out[0] = (float)(tot * (1.0 / ((double)NI * (double)TT)));
        g_acc  = 0.0;               // reset for next graph replay
        g_done = 0;
    }
}

// ======================= launcher ==========================================
extern "C" void kernel_launch(void* const* d_in, const int* in_sizes, int n_in,
                              void* d_out, int out_size) {
    const float* cls    = (const float*)d_in[0];   // [1024,201,100]
    const float* labels = (const float*)d_in[1];   // [1024,201,100]
    float* out = (float*)d_out;

    k_all<<<NI, NTHR>>>(cls, labels, out);
}

// round 9
// speedup vs baseline: 1.3705x; 1.3705x over previous
#include <cuda_runtime.h>
#include <cstdint>
#include <math_constants.h>

#define NI    1024
#define NC    201
#define TT    100
#define ROW   (NC * TT)           // 20100
#define NPAIR (NI * NC)
#define GRID  (2 * NI)            // even bid = label role, odd bid = softplus role

// -------- scratch (no allocations; zero at module load) --------
__device__ double         g_acc;            // running total (reset in tail)
__device__ float          g_sp[NPAIR];      // per-(n,c) softplus sums
__device__ unsigned char  g_wm[NPAIR];      // wm bytes (non-bg rows only; guarded by g_isbg)
__device__ unsigned char  g_isbg[NI];
__device__ float          g_bgGat[NI * 3];  // bg gather range sums [rare, common, freq+bg]
__device__ int            g_rowcnt[NI];     // 2-party handshake per row (reset in tail)
__device__ int            g_done;           // completion counter (reset in tail)

// ======================= threefry2x32 (JAX-exact) =======================
__host__ __device__ constexpr uint32_t rotl32(uint32_t x, int r) {
    return (x << r) | (x >> (32 - r));
}
struct TF2 { uint32_t a, b; };

__host__ __device__ constexpr TF2 tf2x32(uint32_t k0, uint32_t k1,
                                         uint32_t x0, uint32_t x1) {
    uint32_t ks2 = k0 ^ k1 ^ 0x1BD11BDAu;
    uint32_t kk[3] = {k0, k1, ks2};
    const int R0[4] = {13, 15, 26, 6};
    const int R1[4] = {17, 29, 16, 24};
    uint32_t v0 = x0 + k0, v1 = x1 + k1;
    for (int i = 0; i < 5; i++) {
        for (int j = 0; j < 4; j++) {
            int r = (i % 2 == 0) ? R0[j] : R1[j];
            v0 += v1; v1 = rotl32(v1, r); v1 ^= v0;
        }
        v0 += kk[(i + 1) % 3];
        v1 += kk[(i + 2) % 3] + (uint32_t)(i + 1);
    }
    return TF2{v0, v1};
}

constexpr TF2      S98 = tf2x32(0u, 42u, 98u, 198u);
constexpr TF2      S99 = tf2x32(0u, 42u, 99u, 199u);
constexpr uint32_t KLA = S98.b, KLB = S99.b;
constexpr TF2      SP0 = tf2x32(KLA, KLB, 0u, 2u);
constexpr TF2      SP1 = tf2x32(KLA, KLB, 1u, 3u);
constexpr uint32_t K1A = SP0.a, K1B = SP1.a;
constexpr uint32_t K2A = SP0.b, K2B = SP1.b;

__device__ __forceinline__ float tf_uniform(uint32_t ka, uint32_t kb, int n) {
    TF2 r = (n < 512) ? tf2x32(ka, kb, (uint32_t)n,         (uint32_t)(n + 512))
                      : tf2x32(ka, kb, (uint32_t)(n - 512), (uint32_t)n);
    uint32_t bits = (n < 512) ? r.a : r.b;
    return __uint_as_float((bits >> 9) | 0x3f800000u) - 1.0f;
}

// ======================= single kernel, two roles ==========================
__global__ __launch_bounds__(256) void k_main(const float* __restrict__ cls,
                                              const float* __restrict__ labels,
                                              float* __restrict__ out) {
    __shared__ union {
        struct { float best[8][100]; int bi[8][100]; } pa;   // label role
        float part[NC * 25];                                 // sp role (20.1 KB)
        struct { int idx[NI]; float u1[NI]; float u2[NI];
                 unsigned char sel[NI]; } tl;                // tail (13.3 KB)
    } u;
    __shared__ int    sLab[TT];
    __shared__ double sGat[NC];
    __shared__ double sB3[3];
    __shared__ double sRed[8];
    __shared__ int    sSecond, sLast, sCnt;

    int bid  = blockIdx.x;
    int n    = bid >> 1;
    int role = bid & 1;
    int tid  = threadIdx.x;
    int w    = tid >> 5;
    int lane = tid & 31;

    const float* crow = cls + (size_t)n * ROW;

    bool  isbg  = false;
    bool  wmB   = false;   // label role: this thread's wm (tid < NC)
    float spVal = 0.f;     // sp role: this thread's softplus sum (tid < NC)

    if (role == 1) {
        // ================= softplus role: pure stream =================
        if (lane < 25) {
            #pragma unroll 4
            for (int c = w; c < NC; c += 8) {
                float4 x = __ldg((const float4*)(crow + c * TT) + lane);
                float m = fmaxf(x.x, 0.f) + fmaxf(x.y, 0.f)
                        + fmaxf(x.z, 0.f) + fmaxf(x.w, 0.f);
                float l = __log2f(1.f + __expf(-fabsf(x.x)))
                        + __log2f(1.f + __expf(-fabsf(x.y)))
                        + __log2f(1.f + __expf(-fabsf(x.z)))
                        + __log2f(1.f + __expf(-fabsf(x.w)));
                u.part[c * 25 + lane] = m + 0.69314718056f * l;
            }
        }
        __syncthreads();
        if (tid < NC) {
            float s = 0.f;
            #pragma unroll
            for (int i = 0; i < 25; i++) s += u.part[tid * 25 + i];
            spVal = s;
            __stcg(&g_sp[n * NC + tid], s);        // L2 write-through for peer block
        }
    } else {
        // ================= label role: argmax + wm + gather =================
        const float* lrow = labels + (size_t)n * ROW;
        if (tid < NC) sGat[tid] = 0.0;
        if (tid >= NC && tid < NC + 3) sB3[tid - NC] = 0.0;

        if (lane < 25) {
            float b0 = -CUDART_INF_F, b1 = -CUDART_INF_F,
                  b2 = -CUDART_INF_F, b3 = -CUDART_INF_F;
            int i0 = 0, i1 = 0, i2 = 0, i3 = 0;
            #pragma unroll 4
            for (int c = w; c < NC; c += 8) {
                float4 v = __ldg((const float4*)(lrow + c * TT) + lane);
                if (v.x > b0) { b0 = v.x; i0 = c; }
                if (v.y > b1) { b1 = v.y; i1 = c; }
                if (v.z > b2) { b2 = v.z; i2 = c; }
                if (v.w > b3) { b3 = v.w; i3 = c; }
            }
            int t = lane * 4;
            u.pa.best[w][t + 0] = b0; u.pa.bi[w][t + 0] = i0;
            u.pa.best[w][t + 1] = b1; u.pa.bi[w][t + 1] = i1;
            u.pa.best[w][t + 2] = b2; u.pa.bi[w][t + 2] = i2;
            u.pa.best[w][t + 3] = b3; u.pa.bi[w][t + 3] = i3;
        }
        __syncthreads();

        // combine; first-max tie-break (lower c wins)
        if (tid < TT) {
            float b = u.pa.best[0][tid]; int bi = u.pa.bi[0][tid];
            #pragma unroll
            for (int ww = 1; ww < 8; ww++) {
                float v = u.pa.best[ww][tid]; int c = u.pa.bi[ww][tid];
                if (v > b || (v == b && c < bi)) { b = v; bi = c; }
            }
            sLab[tid] = bi;
        }
        __syncthreads();

        int lab99 = sLab[TT - 1];
        isbg = (lab99 == NC - 1);
        if (tid == 0) __stcg(&g_isbg[n], (unsigned char)isbg);

        // gather: sum_t x[n, lab[t], t] binned per class
        if (tid < TT) {
            int lb = sLab[tid];
            atomicAdd(&sGat[lb], (double)__ldg(crow + (size_t)lb * TT + tid));
        }
        __syncthreads();

        double negGat = 0.0;
        if (tid < NC) {
            double g = sGat[tid];
            if (!isbg) {
                float x99 = __ldg(crow + (size_t)tid * TT + 99);
                float sg  = 1.f / (1.f + __expf(-x99));
                wmB = (tid == lab99) || (sg >= 0.3f);
                __stcg(&g_wm[n * NC + tid], (unsigned char)wmB);
                if (wmB) negGat = g;
            } else if (g != 0.0) {
                int r = (tid >= 150) ? 2 : (tid >= 50 ? 1 : 0);
                atomicAdd(&sB3[r], g);
            }
        }
        #pragma unroll
        for (int o = 16; o; o >>= 1)
            negGat += __shfl_xor_sync(0xffffffffu, negGat, o);
        if (lane == 0) sRed[w] = negGat;
        __syncthreads();
        if (tid == 0 && !isbg) {
            double s = 0.0;
            #pragma unroll
            for (int i = 0; i < 8; i++) s += sRed[i];
            atomicAdd(&g_acc, -s);
        }
        if (isbg && tid < 3) __stcg(&g_bgGat[n * 3 + tid], (float)sB3[tid]);
    }

    // ================= per-row handshake: second finisher does the dot =======
    __syncthreads();                 // all sRed reads done before reuse below
    if (tid == 0) {
        __threadfence();
        sSecond = (atomicAdd(&g_rowcnt[n], 1) == 1);
    }
    __syncthreads();
    if (sSecond) {
        __threadfence();
        bool bg = role ? (__ldcg(&g_isbg[n]) != 0) : isbg;
        if (!bg) {
            double wv = 0.0;
            if (tid < NC) {
                if (role == 1) {
                    if (__ldcg(&g_wm[n * NC + tid])) wv = (double)spVal;
                } else {
                    if (wmB) wv = (double)__ldcg(&g_sp[n * NC + tid]);
                }
            }
            #pragma unroll
            for (int o = 16; o; o >>= 1) wv += __shfl_xor_sync(0xffffffffu, wv, o);
            if (lane == 0) sRed[w] = wv;
            __syncthreads();
            if (tid == 0) {
                double s = 0.0;
                #pragma unroll
                for (int i = 0; i < 8; i++) s += sRed[i];
                atomicAdd(&g_acc, s);
            }
        }
    }

    // ================= completion; last block runs bg tail ===================
    __syncthreads();
    if (tid == 0) {
        __threadfence();
        sLast = (atomicAdd(&g_done, 1) == GRID - 1);
    }
    __syncthreads();
    if (!sLast) return;
    __threadfence();

    if (tid == 0) sCnt = 0;
    __syncthreads();

    for (int i = tid; i < NI; i += 256) {
        g_rowcnt[i] = 0;                       // reset handshake for next replay
        if (__ldcg(&g_isbg[i])) {
            int p = atomicAdd(&sCnt, 1);
            u.tl.idx[p] = i;
            u.tl.u1[p]  = tf_uniform(K1A, K1B, i);
            u.tl.u2[p]  = tf_uniform(K2A, K2B, i);
        }
    }
    __syncthreads();

    int nbg = sCnt;
    int kr  = nbg / 100;            // int(n_bg * 0.01)
    int kc  = nbg / 10;             // int(n_bg * 0.10)

    // stable-argsort ranks among bg rows
    for (int i = tid; i < nbg; i += 256) {
        float u1 = u.tl.u1[i], u2 = u.tl.u2[i];
        int   m  = u.tl.idx[i];
        int r1 = 0, r2 = 0;
        for (int j = 0; j < nbg; j++) {
            float a = u.tl.u1[j], b = u.tl.u2[j];
            int  mj = u.tl.idx[j];
            r1 += (a < u1) || (a == u1 && mj < m);
            r2 += (b < u2) || (b == u2 && mj < m);
        }
        u.tl.sel[i] = (unsigned char)((r1 < kr ? 2u : 0u) | (r2 < kc ? 4u : 0u));
    }
    __syncthreads();

    // bg contributions: + wm-masked softplus (from g_sp), - gather range sums
    double acc = 0.0;
    for (int q = tid; q < nbg * NC; q += 256) {
        int i = q / NC;
        int c = q - i * NC;
        unsigned f = u.tl.sel[i];
        bool wm = (c >= 150) || ((f & 2u) && c < 50) ||
                  ((f & 4u) && c >= 50 && c < 150);
        if (wm) acc += (double)__ldcg(&g_sp[u.tl.idx[i] * NC + c]);
    }
    for (int i = tid; i < nbg; i += 256) {
        const float* G = &g_bgGat[u.tl.idx[i] * 3];
        unsigned f = u.tl.sel[i];
        acc -= (double)__ldcg(&G[2]);
        if (f & 2u) acc -= (double)__ldcg(&G[0]);
        if (f & 4u) acc -= (double)__ldcg(&G[1]);
    }
    #pragma unroll
    for (int o = 16; o; o >>= 1) acc += __shfl_xor_sync(0xffffffffu, acc, o);
    if (lane == 0) sRed[w] = acc;
    __syncthreads();
    if (tid == 0) {
        double s = 0.0;
        #pragma unroll
        for (int i = 0; i < 8; i++) s += sRed[i];
        double tot = atomicAdd(&g_acc, 0.0) + s;
        out[0] = (float)(tot * (1.0 / ((double)NI * (double)TT)));
        g_acc  = 0.0;               // reset for next graph replay
        g_done = 0;
    }
}

// ======================= launcher ==========================================
extern "C" void kernel_launch(void* const* d_in, const int* in_sizes, int n_in,
                              void* d_out, int out_size) {
    const float* cls    = (const float*)d_in[0];   // [1024,201,100]
    const float* labels = (const float*)d_in[1];   // [1024,201,100]
    float* out = (float*)d_out;

    k_main<<<GRID, 256>>>(cls, labels, out);
}

// round 10
// speedup vs baseline: 1.3767x; 1.0045x over previous
#include <cuda_runtime.h>
#include <cstdint>
#include <math_constants.h>

#define NI    1024
#define NC    201
#define TT    100
#define ROW   (NC * TT)           // 20100
#define NPAIR (NI * NC)
#define NQ4   (NC * 25)           // 5025 float4 per row
#define GRID  (2 * NI)            // even bid = label role, odd bid = softplus role

// -------- scratch (no allocations; zero at module load) --------
__device__ double g_acc;            // running total (reset in tail)
__device__ float  g_sp[NPAIR];      // per-(n,c) softplus sums
__device__ float  g_spThr[NI];      // per-row thresholded softplus sum
__device__ float  g_spRg[NI * 3];   // per-row sp range sums [rare, common, freq+bg]
__device__ float  g_bgGat[NI * 3];  // bg gather range sums
__device__ int    g_fix[NI];        // -2 = bg row, -1 = no fix, >=0 = lab99 needing fix
__device__ int    g_rowcnt[NI];     // 2-party handshake (reset in tail)
__device__ int    g_done;           // completion counter (reset in tail)

// ======================= threefry2x32 (JAX-exact) =======================
__host__ __device__ constexpr uint32_t rotl32(uint32_t x, int r) {
    return (x << r) | (x >> (32 - r));
}
struct TF2 { uint32_t a, b; };

__host__ __device__ constexpr TF2 tf2x32(uint32_t k0, uint32_t k1,
                                         uint32_t x0, uint32_t x1) {
    uint32_t ks2 = k0 ^ k1 ^ 0x1BD11BDAu;
    uint32_t kk[3] = {k0, k1, ks2};
    const int R0[4] = {13, 15, 26, 6};
    const int R1[4] = {17, 29, 16, 24};
    uint32_t v0 = x0 + k0, v1 = x1 + k1;
    for (int i = 0; i < 5; i++) {
        for (int j = 0; j < 4; j++) {
            int r = (i % 2 == 0) ? R0[j] : R1[j];
            v0 += v1; v1 = rotl32(v1, r); v1 ^= v0;
        }
        v0 += kk[(i + 1) % 3];
        v1 += kk[(i + 2) % 3] + (uint32_t)(i + 1);
    }
    return TF2{v0, v1};
}

constexpr TF2      S98 = tf2x32(0u, 42u, 98u, 198u);
constexpr TF2      S99 = tf2x32(0u, 42u, 99u, 199u);
constexpr uint32_t KLA = S98.b, KLB = S99.b;
constexpr TF2      SP0 = tf2x32(KLA, KLB, 0u, 2u);
constexpr TF2      SP1 = tf2x32(KLA, KLB, 1u, 3u);
constexpr uint32_t K1A = SP0.a, K1B = SP1.a;
constexpr uint32_t K2A = SP0.b, K2B = SP1.b;

__device__ __forceinline__ float tf_uniform(uint32_t ka, uint32_t kb, int n) {
    TF2 r = (n < 512) ? tf2x32(ka, kb, (uint32_t)n,         (uint32_t)(n + 512))
                      : tf2x32(ka, kb, (uint32_t)(n - 512), (uint32_t)n);
    uint32_t bits = (n < 512) ? r.a : r.b;
    return __uint_as_float((bits >> 9) | 0x3f800000u) - 1.0f;
}

// ======================= single kernel, two roles ==========================
__global__ __launch_bounds__(256) void k_main(const float* __restrict__ cls,
                                              const float* __restrict__ labels,
                                              float* __restrict__ out) {
    __shared__ union {
        struct { float best[8][100]; int bi[8][100]; } pa;   // label role (6.4 KB)
        float part[NQ4];                                     // sp role (20.1 KB)
        struct { int idx[NI]; float u1[NI]; float u2[NI];
                 unsigned char sel[NI]; } tl;                // tail (13.3 KB)
    } u;
    __shared__ float  sS[NC];
    __shared__ int    sLab[TT];
    __shared__ double sGat[NC];
    __shared__ double sB3[3];
    __shared__ double sRed[8];
    __shared__ float  sSthr;
    __shared__ int    sFix, sSecond, sLast, sCnt;

    const int bid  = blockIdx.x;
    const int n    = bid >> 1;
    const int role = bid & 1;
    const int tid  = threadIdx.x;
    const int w    = tid >> 5;
    const int lane = tid & 31;

    const float* crow = cls + (size_t)n * ROW;
    bool isbg = false;

    if (role == 1) {
        // ================= softplus role: full-lane pure stream =================
        #pragma unroll 4
        for (int q = tid; q < NQ4; q += 256) {
            float4 x = __ldg((const float4*)crow + q);
            float m = fmaxf(x.x, 0.f) + fmaxf(x.y, 0.f)
                    + fmaxf(x.z, 0.f) + fmaxf(x.w, 0.f);
            float l = __log2f(1.f + __expf(-fabsf(x.x)))
                    + __log2f(1.f + __expf(-fabsf(x.y)))
                    + __log2f(1.f + __expf(-fabsf(x.z)))
                    + __log2f(1.f + __expf(-fabsf(x.w)));
            u.part[q] = m + 0.69314718056f * l;
        }
        __syncthreads();

        float thr = 0.f;
        if (tid < NC) {
            float s = 0.f;
            #pragma unroll
            for (int i = 0; i < 25; i++) s += u.part[tid * 25 + i];
            sS[tid] = s;
            g_sp[n * NC + tid] = s;
            float x99 = __ldg(crow + (size_t)tid * TT + (TT - 1));  // L1/L2 hit
            float sg  = 1.f / (1.f + __expf(-x99));
            if (sg >= 0.3f) thr = s;
        }
        #pragma unroll
        for (int o = 16; o; o >>= 1) thr += __shfl_xor_sync(0xffffffffu, thr, o);
        if (lane == 0) sRed[w] = (double)thr;
        __syncthreads();
        if (tid == 0) {
            double t = 0.0;
            #pragma unroll
            for (int i = 0; i < 8; i++) t += sRed[i];
            sSthr = (float)t;
            g_spThr[n] = (float)t;
        }
        // per-range sp sums (always computed; used only if row is bg)
        if (tid == 1) { float r = 0.f; for (int c = 0;   c < 50;  c++) r += sS[c]; g_spRg[n*3+0] = r; }
        if (tid == 2) { float r = 0.f; for (int c = 50;  c < 150; c++) r += sS[c]; g_spRg[n*3+1] = r; }
        if (tid == 3) { float r = 0.f; for (int c = 150; c < NC;  c++) r += sS[c]; g_spRg[n*3+2] = r; }
    } else {
        // ================= label role: argmax + gather dot =================
        const float* lrow = labels + (size_t)n * ROW;
        if (tid == 0) sFix = -1;
        if (tid < NC) sGat[tid] = 0.0;
        if (tid >= NC && tid < NC + 3) sB3[tid - NC] = 0.0;

        if (lane < 25) {
            float b0 = -CUDART_INF_F, b1 = -CUDART_INF_F,
                  b2 = -CUDART_INF_F, b3 = -CUDART_INF_F;
            int i0 = 0, i1 = 0, i2 = 0, i3 = 0;
            #pragma unroll 4
            for (int c = w; c < NC; c += 8) {
                float4 v = __ldg((const float4*)(lrow + c * TT) + lane);
                if (v.x > b0) { b0 = v.x; i0 = c; }
                if (v.y > b1) { b1 = v.y; i1 = c; }
                if (v.z > b2) { b2 = v.z; i2 = c; }
                if (v.w > b3) { b3 = v.w; i3 = c; }
            }
            int t = lane * 4;
            u.pa.best[w][t + 0] = b0; u.pa.bi[w][t + 0] = i0;
            u.pa.best[w][t + 1] = b1; u.pa.bi[w][t + 1] = i1;
            u.pa.best[w][t + 2] = b2; u.pa.bi[w][t + 2] = i2;
            u.pa.best[w][t + 3] = b3; u.pa.bi[w][t + 3] = i3;
        }
        __syncthreads();

        // combine; first-max tie-break (lower c wins)
        if (tid < TT) {
            float b = u.pa.best[0][tid]; int bi = u.pa.bi[0][tid];
            #pragma unroll
            for (int ww = 1; ww < 8; ww++) {
                float v = u.pa.best[ww][tid]; int c = u.pa.bi[ww][tid];
                if (v > b || (v == b && c < bi)) { b = v; bi = c; }
            }
            sLab[tid] = bi;
        }
        __syncthreads();

        int lab99 = sLab[TT - 1];
        isbg = (lab99 == NC - 1);

        // gather: sum_t x[n, lab[t], t] binned per class
        if (tid < TT) {
            int lb = sLab[tid];
            atomicAdd(&sGat[lb], (double)__ldg(crow + (size_t)lb * TT + tid));
        }
        __syncthreads();

        double neg = 0.0;
        if (tid < NC) {
            double g = sGat[tid];
            if (!isbg) {
                if (g != 0.0 || tid == lab99) {   // only classes that matter load x99
                    float x99 = __ldg(crow + (size_t)tid * TT + (TT - 1));
                    float sg  = 1.f / (1.f + __expf(-x99));
                    bool wm = (tid == lab99) || (sg >= 0.3f);
                    if (wm) neg = g;
                    if (tid == lab99 && sg < 0.3f) sFix = lab99;  // sp[lab99] fix needed
                }
            } else if (g != 0.0) {
                int r = (tid >= 150) ? 2 : (tid >= 50 ? 1 : 0);
                atomicAdd(&sB3[r], g);
            }
        }
        #pragma unroll
        for (int o = 16; o; o >>= 1) neg += __shfl_xor_sync(0xffffffffu, neg, o);
        if (lane == 0) sRed[w] = neg;
        __syncthreads();
        if (tid == 0) {
            g_fix[n] = isbg ? -2 : sFix;
            if (!isbg) {
                double s = 0.0;
                #pragma unroll
                for (int i = 0; i < 8; i++) s += sRed[i];
                atomicAdd(&g_acc, -s);
            }
        }
        if (isbg && tid < 3) g_bgGat[n * 3 + tid] = (float)sB3[tid];
    }

    // ========= per-row handshake: second finisher (tid 0 only, ~2 loads) =========
    __syncthreads();
    if (tid == 0) {
        __threadfence();
        sSecond = (atomicAdd(&g_rowcnt[n], 1) == 1);
    }
    __syncthreads();
    if (tid == 0 && sSecond) {
        __threadfence();
        if (role == 1) {
            int f = __ldcg(&g_fix[n]);
            if (f != -2) {
                double a = (double)sSthr + (f >= 0 ? (double)sS[f] : 0.0);
                atomicAdd(&g_acc, a);
            }
        } else if (!isbg) {
            double a = (double)__ldcg(&g_spThr[n]);
            int f = sFix;
            if (f >= 0) a += (double)__ldcg(&g_sp[n * NC + f]);
            atomicAdd(&g_acc, a);
        }
    }

    // ================= completion; last block runs bg tail ===================
    __syncthreads();
    if (tid == 0) {
        __threadfence();
        sLast = (atomicAdd(&g_done, 1) == GRID - 1);
    }
    __syncthreads();
    if (!sLast) return;
    __threadfence();

    if (tid == 0) sCnt = 0;
    __syncthreads();

    for (int i = tid; i < NI; i += 256) {
        g_rowcnt[i] = 0;                       // reset handshake for next replay
        if (__ldcg(&g_fix[i]) == -2) {
            int p = atomicAdd(&sCnt, 1);
            u.tl.idx[p] = i;
            u.tl.u1[p]  = tf_uniform(K1A, K1B, i);
            u.tl.u2[p]  = tf_uniform(K2A, K2B, i);
        }
    }
    __syncthreads();

    int nbg = sCnt;
    int kr  = nbg / 100;            // int(n_bg * 0.01)
    int kc  = nbg / 10;             // int(n_bg * 0.10)

    // stable-argsort ranks among bg rows
    for (int i = tid; i < nbg; i += 256) {
        float u1 = u.tl.u1[i], u2 = u.tl.u2[i];
        int   m  = u.tl.idx[i];
        int r1 = 0, r2 = 0;
        for (int j = 0; j < nbg; j++) {
            float a = u.tl.u1[j], b = u.tl.u2[j];
            int  mj = u.tl.idx[j];
            r1 += (a < u1) || (a == u1 && mj < m);
            r2 += (b < u2) || (b == u2 && mj < m);
        }
        u.tl.sel[i] = (unsigned char)((r1 < kr ? 2u : 0u) | (r2 < kc ? 4u : 0u));
    }
    __syncthreads();

    // bg contributions from range sums: wm * (sp - gather) per range
    double acc = 0.0;
    for (int i = tid; i < nbg; i += 256) {
        int nn = u.tl.idx[i];
        unsigned f = u.tl.sel[i];
        const float* SR = &g_spRg[nn * 3];
        const float* GR = &g_bgGat[nn * 3];
        acc += (double)__ldcg(&SR[2]) - (double)__ldcg(&GR[2]);          // freq+bg
        if (f & 2u) acc += (double)__ldcg(&SR[0]) - (double)__ldcg(&GR[0]);  // rare
        if (f & 4u) acc += (double)__ldcg(&SR[1]) - (double)__ldcg(&GR[1]);  // common
    }
    #pragma unroll
    for (int o = 16; o; o >>= 1) acc += __shfl_xor_sync(0xffffffffu, acc, o);
    if (lane == 0) sRed[w] = acc;
    __syncthreads();
    if (tid == 0) {
        double s = 0.0;
        #pragma unroll
        for (int i = 0; i < 8; i++) s += sRed[i];
        double tot = atomicAdd(&g_acc, 0.0) + s;
        out[0] = (float)(tot * (1.0 / ((double)NI * (double)TT)));
        g_acc  = 0.0;               // reset for next graph replay
        g_done = 0;
    }
}

// ======================= launcher ==========================================
extern "C" void kernel_launch(void* const* d_in, const int* in_sizes, int n_in,
                              void* d_out, int out_size) {
    const float* cls    = (const float*)d_in[0];   // [1024,201,100]
    const float* labels = (const float*)d_in[1];   // [1024,201,100]
    float* out = (float*)d_out;

    k_main<<<GRID, 256>>>(cls, labels, out);
}

// round 11
// speedup vs baseline: 1.4972x; 1.0875x over previous
#include <cuda_runtime.h>
#include <cstdint>
#include <math_constants.h>

#define NI    1024
#define NC    201
#define TT    100
#define ROW   (NC * TT)           // 20100
#define NPAIR (NI * NC)
#define NQ4   (NC * 25)           // 5025 float4 per row
#define TOT4  (NI * NQ4)          // 5,145,600
#define GRID2 1184                // k_sp grid

// -------- scratch (no allocations; zero at module load) --------
__device__ double         g_acc;            // running total (reset by k_sp tail)
__device__ unsigned char  g_wm[NPAIR];      // weight mask bytes (fully rewritten each run)
__device__ unsigned char  g_isbg[NI];
__device__ float          g_bgGat[NI * 3];  // bg gather range sums [rare, common, freq+bg]
__device__ int            g_done1;          // k_lab completion counter (reset by its tail)
__device__ int            g_done2;          // k_sp completion counter (reset by its tail)

// ======================= threefry2x32 (JAX-exact) =======================
__host__ __device__ constexpr uint32_t rotl32(uint32_t x, int r) {
    return (x << r) | (x >> (32 - r));
}
struct TF2 { uint32_t a, b; };

__host__ __device__ constexpr TF2 tf2x32(uint32_t k0, uint32_t k1,
                                         uint32_t x0, uint32_t x1) {
    uint32_t ks2 = k0 ^ k1 ^ 0x1BD11BDAu;
    uint32_t kk[3] = {k0, k1, ks2};
    const int R0[4] = {13, 15, 26, 6};
    const int R1[4] = {17, 29, 16, 24};
    uint32_t v0 = x0 + k0, v1 = x1 + k1;
    for (int i = 0; i < 5; i++) {
        for (int j = 0; j < 4; j++) {
            int r = (i % 2 == 0) ? R0[j] : R1[j];
            v0 += v1; v1 = rotl32(v1, r); v1 ^= v0;
        }
        v0 += kk[(i + 1) % 3];
        v1 += kk[(i + 2) % 3] + (uint32_t)(i + 1);
    }
    return TF2{v0, v1};
}

constexpr TF2      S98 = tf2x32(0u, 42u, 98u, 198u);
constexpr TF2      S99 = tf2x32(0u, 42u, 99u, 199u);
constexpr uint32_t KLA = S98.b, KLB = S99.b;
constexpr TF2      SP0 = tf2x32(KLA, KLB, 0u, 2u);
constexpr TF2      SP1 = tf2x32(KLA, KLB, 1u, 3u);
constexpr uint32_t K1A = SP0.a, K1B = SP1.a;
constexpr uint32_t K2A = SP0.b, K2B = SP1.b;

__device__ __forceinline__ float tf_uniform(uint32_t ka, uint32_t kb, int n) {
    TF2 r = (n < 512) ? tf2x32(ka, kb, (uint32_t)n,         (uint32_t)(n + 512))
                      : tf2x32(ka, kb, (uint32_t)(n - 512), (uint32_t)n);
    uint32_t bits = (n < 512) ? r.a : r.b;
    return __uint_as_float((bits >> 9) | 0x3f800000u) - 1.0f;
}

// ======================= K1: labels stream + wm + gather + tail ============
__global__ __launch_bounds__(256) void k_lab(const float* __restrict__ labels,
                                             const float* __restrict__ cls) {
    __shared__ union {
        struct { float best[8][100]; int bi[8][100]; } pa;   // argmax (6.4 KB)
        struct { int idx[NI]; float u1[NI]; float u2[NI];
                 unsigned char sel[NI]; } tl;                // tail (13.3 KB)
    } u;
    __shared__ int    sLab[TT];
    __shared__ double sGat[NC];
    __shared__ float  sG3[3];
    __shared__ double sRed[8];
    __shared__ int    sLast, sCnt;

    const int n    = blockIdx.x;
    const int tid  = threadIdx.x;
    const int w    = tid >> 5;
    const int lane = tid & 31;

    if (tid < NC) sGat[tid] = 0.0;
    if (tid >= NC && tid < NC + 3) sG3[tid - NC] = 0.f;

    const float* lrow = labels + (size_t)n * ROW;
    const float* crow = cls    + (size_t)n * ROW;

    // ---- per-warp partial argmax over strided class subset ----
    if (lane < 25) {
        float b0 = -CUDART_INF_F, b1 = -CUDART_INF_F,
              b2 = -CUDART_INF_F, b3 = -CUDART_INF_F;
        int i0 = 0, i1 = 0, i2 = 0, i3 = 0;
        #pragma unroll 4
        for (int c = w; c < NC; c += 8) {
            float4 v = __ldg((const float4*)(lrow + c * TT) + lane);
            if (v.x > b0) { b0 = v.x; i0 = c; }
            if (v.y > b1) { b1 = v.y; i1 = c; }
            if (v.z > b2) { b2 = v.z; i2 = c; }
            if (v.w > b3) { b3 = v.w; i3 = c; }
        }
        int t = lane * 4;
        u.pa.best[w][t + 0] = b0; u.pa.bi[w][t + 0] = i0;
        u.pa.best[w][t + 1] = b1; u.pa.bi[w][t + 1] = i1;
        u.pa.best[w][t + 2] = b2; u.pa.bi[w][t + 2] = i2;
        u.pa.best[w][t + 3] = b3; u.pa.bi[w][t + 3] = i3;
    }
    __syncthreads();

    // ---- combine partials; first-max tie-break (lower c wins) ----
    if (tid < TT) {
        float b = u.pa.best[0][tid]; int bi = u.pa.bi[0][tid];
        #pragma unroll
        for (int ww = 1; ww < 8; ww++) {
            float v = u.pa.best[ww][tid]; int c = u.pa.bi[ww][tid];
            if (v > b || (v == b && c < bi)) { b = v; bi = c; }
        }
        sLab[tid] = bi;
    }
    __syncthreads();

    const int  lab99 = sLab[TT - 1];
    const bool isbg  = (lab99 == NC - 1);
    if (tid == 0) g_isbg[n] = (unsigned char)isbg;

    // ---- gather: sum_t x[n, lab[t], t] binned per class ----
    if (tid < TT) {
        int lb = sLab[tid];
        atomicAdd(&sGat[lb], (double)__ldg(crow + (size_t)lb * TT + tid));
    }
    __syncthreads();

    // ---- per-class: wm (non-bg) + gather dot; bg -> range partials ----
    float neg = 0.f;
    if (tid < NC) {
        float g = (float)sGat[tid];
        if (!isbg) {
            float x99 = __ldg(crow + (size_t)tid * TT + (TT - 1));
            float sg  = 1.f / (1.f + __expf(-x99));
            bool wm = (tid == lab99) || (sg >= 0.3f);
            g_wm[n * NC + tid] = (unsigned char)wm;
            if (wm) neg = g;
        } else if (g != 0.f) {
            int r = (tid >= 150) ? 2 : (tid >= 50 ? 1 : 0);
            atomicAdd(&sG3[r], g);
        }
    }

    // block reduce of gather dot (non-bg)
    #pragma unroll
    for (int o = 16; o; o >>= 1) neg += __shfl_xor_sync(0xffffffffu, neg, o);
    if (lane == 0) sRed[w] = (double)neg;
    __syncthreads();
    if (tid == 0 && !isbg) {
        double s = 0.0;
        #pragma unroll
        for (int i = 0; i < 8; i++) s += sRed[i];
        atomicAdd(&g_acc, -s);
    }
    if (isbg && tid < 3) g_bgGat[n * 3 + tid] = sG3[tid];

    // ================= last-done block: bg selection tail =================
    __syncthreads();                      // u.pa reads complete before union reuse
    if (tid == 0) {
        __threadfence();
        sLast = (atomicAdd(&g_done1, 1) == NI - 1);
    }
    __syncthreads();
    if (!sLast) return;
    __threadfence();

    if (tid == 0) sCnt = 0;
    __syncthreads();

    // compact bg rows + uniforms
    for (int i = tid; i < NI; i += 256) {
        if (__ldcg(&g_isbg[i])) {
            int p = atomicAdd(&sCnt, 1);
            u.tl.idx[p] = i;
            u.tl.u1[p]  = tf_uniform(K1A, K1B, i);
            u.tl.u2[p]  = tf_uniform(K2A, K2B, i);
        }
    }
    __syncthreads();

    const int nbg = sCnt;
    const int kr  = nbg / 100;            // int(n_bg * 0.01)
    const int kc  = nbg / 10;             // int(n_bg * 0.10)

    // stable-argsort ranks among bg rows
    for (int i = tid; i < nbg; i += 256) {
        float u1 = u.tl.u1[i], u2 = u.tl.u2[i];
        int   m  = u.tl.idx[i];
        int r1 = 0, r2 = 0;
        for (int j = 0; j < nbg; j++) {
            float a = u.tl.u1[j], b = u.tl.u2[j];
            int  mj = u.tl.idx[j];
            r1 += (a < u1) || (a == u1 && mj < m);
            r2 += (b < u2) || (b == u2 && mj < m);
        }
        u.tl.sel[i] = (unsigned char)((r1 < kr ? 2u : 0u) | (r2 < kc ? 4u : 0u));
    }
    __syncthreads();

    // bg wm bytes (read by k_sp)
    for (int q = tid; q < nbg * NC; q += 256) {
        int i = q / NC;
        int c = q - i * NC;
        unsigned f = u.tl.sel[i];
        bool wm = (c >= 150) || ((f & 2u) && c < 50) ||
                  ((f & 4u) && c >= 50 && c < 150);
        g_wm[u.tl.idx[i] * NC + c] = (unsigned char)wm;
    }

    // bg gather dot (negative contribution)
    double acc = 0.0;
    for (int i = tid; i < nbg; i += 256) {
        const float* G = &g_bgGat[u.tl.idx[i] * 3];
        unsigned f = u.tl.sel[i];
        acc += (double)__ldcg(&G[2]);
        if (f & 2u) acc += (double)__ldcg(&G[0]);
        if (f & 4u) acc += (double)__ldcg(&G[1]);
    }
    #pragma unroll
    for (int o = 16; o; o >>= 1) acc += __shfl_xor_sync(0xffffffffu, acc, o);
    if (lane == 0) sRed[w] = acc;
    __syncthreads();
    if (tid == 0) {
        double s = 0.0;
        #pragma unroll
        for (int i = 0; i < 8; i++) s += sRed[i];
        atomicAdd(&g_acc, -s);
        g_done1 = 0;                      // reset for next graph replay
    }
}

// ======================= K2: flat masked softplus stream + finalize ========
__global__ __launch_bounds__(256) void k_sp(const float* __restrict__ cls,
                                            float* __restrict__ out) {
    __shared__ double sRed[8];
    __shared__ int    sLast;

    const int tid  = threadIdx.x;
    const int w    = tid >> 5;
    const int lane = tid & 31;
    const int stride = GRID2 * 256;

    float acc = 0.f;
    for (int q = blockIdx.x * 256 + tid; q < TOT4; q += stride) {
        if (g_wm[q / 25]) {                       // skip dead classes (~20%)
            float4 x = __ldg((const float4*)cls + q);
            float m = fmaxf(x.x, 0.f) + fmaxf(x.y, 0.f)
                    + fmaxf(x.z, 0.f) + fmaxf(x.w, 0.f);
            float l = __log2f(1.f + __expf(-fabsf(x.x)))
                    + __log2f(1.f + __expf(-fabsf(x.y)))
                    + __log2f(1.f + __expf(-fabsf(x.z)))
                    + __log2f(1.f + __expf(-fabsf(x.w)));
            acc += m + 0.69314718056f * l;
        }
    }

    double d = (double)acc;
    #pragma unroll
    for (int o = 16; o; o >>= 1) d += __shfl_xor_sync(0xffffffffu, d, o);
    if (lane == 0) sRed[w] = d;
    __syncthreads();
    if (tid == 0) {
        double s = 0.0;
        #pragma unroll
        for (int i = 0; i < 8; i++) s += sRed[i];
        atomicAdd(&g_acc, s);
        __threadfence();
        sLast = (atomicAdd(&g_done2, 1) == GRID2 - 1);
    }
    __syncthreads();
    if (sLast && tid == 0) {
        double tot = atomicAdd(&g_acc, 0.0);      // all contributions visible
        out[0] = (float)(tot * (1.0 / ((double)NI * (double)TT)));
        g_acc   = 0.0;                            // reset for next graph replay
        g_done2 = 0;
    }
}

// ======================= launcher ==========================================
extern "C" void kernel_launch(void* const* d_in, const int* in_sizes, int n_in,
                              void* d_out, int out_size) {
    const float* cls    = (const float*)d_in[0];   // [1024,201,100]
    const float* labels = (const float*)d_in[1];   // [1024,201,100]
    float* out = (float*)d_out;

    k_lab<<<NI, 256>>>(labels, cls);
    k_sp <<<GRID2, 256>>>(cls, out);
}